// round 11
// baseline (speedup 1.0000x reference)
#include <cuda_runtime.h>

// ScatterLoss — per-class contrastive hinge loss.
// d_in[0] = output [N, D] float32 (N=65536, D=512)
// d_in[1] = label_id [N] int32
// out     = scalar float32
//
// loss = (1/N) * sum_k cnt_k * relu(1 - || s_k/c_k - (T - s_k)/(N - c_k) + 1e-6 ||_2)^2

#define NCLS 512
#define DDIM 512
#define CAP  1024          // max rows per class (counts ~128±11)
#define NSPL 4             // class split factor for the streaming kernel
#define PAD  32            // ints per 128B line — atomic-target padding
#define NCTA (NCLS * NSPL) // 2048 gather CTAs
#define VOL  32            // volunteer CTAs that run the fused epilogue

// Zeroed each replay by one memset node (0 bits == 0.0f == 0).
struct ZeroBlk {
    int   cnt[NCLS * PAD];
    float d2[NCLS * PAD];
    unsigned int tkt1;
    unsigned int tkt2;
    int   flag;
};
static __device__ ZeroBlk g_z;

static __device__ int   g_idx[NCLS * CAP];
static __device__ float g_sumsp[NSPL][NCLS][DDIM];   // per-quarter class sums

// ---------------------------------------------------------------------------
// K1: counting-sort scatter (R7-proven config: one thread per label).
// Padded counters spread 65K atomics over 512 distinct 128B lines.
// ---------------------------------------------------------------------------
__global__ void k_scatter(const int* __restrict__ lab, int N)
{
    int i = blockIdx.x * blockDim.x + threadIdx.x;
    if (i < N) {
        int k = lab[i];
        if ((unsigned)k < NCLS) {
            int pos = atomicAdd(&g_z.cnt[k * PAD], 1);
            if (pos < CAP) g_idx[k * CAP + pos] = i;
        }
    }
}

// ---------------------------------------------------------------------------
// K2 (fused): per-class partial sums + inline epilogue.
// Gather phase (all 2048 CTAs): four CTAs per class, contiguous quarters of
// the row list; warp-uniform index loads (broadcast); 2KB coalesced float4
// row reads, __ldcs evict-first, unroll 8. Reads the 128 MB matrix once.
// Epilogue (last VOL=32 ticket holders): after the flag CTA (ticket 2047)
// signals completion, each volunteer processes 4 float4-columns — grand
// total via block tree-reduce, per-class d^2 deposits (padded atomics) —
// and the last volunteer (ticket2) does hinge + count-weighted mean.
// ---------------------------------------------------------------------------
__global__ void __launch_bounds__(128, 8)
k_fused(const float* __restrict__ out, float* __restrict__ outp, float fN)
{
    // ---------------- gather phase ----------------
    int k  = blockIdx.x >> 2;
    int h  = blockIdx.x & 3;
    int nk = min(g_z.cnt[k * PAD], CAP);
    int j0 = (h * nk) >> 2;
    int j1 = ((h + 1) * nk) >> 2;
    int nj = j1 - j0;

    const int* idx = g_idx + k * CAP + j0;
    int q = threadIdx.x;  // float4 column 0..127

    float4 acc = make_float4(0.f, 0.f, 0.f, 0.f);
    #pragma unroll 8
    for (int j = 0; j < nj; j++) {
        int r = __ldg(idx + j);                       // uniform -> broadcast
        const float4* row = (const float4*)(out + (size_t)r * DDIM);
        float4 v = __ldcs(row + q);                   // read-once: evict-first
        acc.x += v.x; acc.y += v.y; acc.z += v.z; acc.w += v.w;
    }
    ((float4*)g_sumsp[h][k])[q] = acc;

    // ---------------- ticket ----------------
    __shared__ unsigned int s_t;
    __threadfence();                                   // publish my quarter-sum
    __syncthreads();
    if (threadIdx.x == 0) s_t = atomicAdd(&g_z.tkt1, 1u);
    __syncthreads();
    unsigned int tk = s_t;

    if (tk == NCTA - 1) {                              // I am last: open the gate
        __threadfence();
        atomicExch(&g_z.flag, 1);
    }
    if (tk < NCTA - VOL) return;                       // non-volunteers done

    // ---------------- volunteer epilogue ----------------
    int tile = (int)(tk - (NCTA - VOL));               // 0..31
    int cg0  = tile * 4;                               // 4 float4-cols per tile
    int t    = threadIdx.x;

    if (t == 0) {
        while (atomicAdd(&g_z.flag, 0) == 0) __nanosleep(64);
    }
    __syncthreads();
    __threadfence();                                   // acquire everyone's sums

    __shared__ float4 red[4][128];

    // pass 1: grand totals for this tile's 4 columns
    float4 Tt[4];
    #pragma unroll
    for (int cc = 0; cc < 4; cc++) Tt[cc] = make_float4(0.f, 0.f, 0.f, 0.f);
    #pragma unroll
    for (int j = 0; j < 4; j++) {
        int kk = t + j * 128;
        #pragma unroll
        for (int cc = 0; cc < 4; cc++) {
            #pragma unroll
            for (int hh = 0; hh < NSPL; hh++) {
                float4 v = ((const float4*)g_sumsp[hh][kk])[cg0 + cc];
                Tt[cc].x += v.x; Tt[cc].y += v.y; Tt[cc].z += v.z; Tt[cc].w += v.w;
            }
        }
    }
    #pragma unroll
    for (int cc = 0; cc < 4; cc++) red[cc][t] = Tt[cc];
    __syncthreads();
    #pragma unroll
    for (int sh = 64; sh > 0; sh >>= 1) {
        if (t < sh) {
            #pragma unroll
            for (int cc = 0; cc < 4; cc++) {
                float4 b = red[cc][t + sh];
                red[cc][t].x += b.x; red[cc][t].y += b.y;
                red[cc][t].z += b.z; red[cc][t].w += b.w;
            }
        }
        __syncthreads();
    }
    #pragma unroll
    for (int cc = 0; cc < 4; cc++) Tt[cc] = red[cc][0];

    // pass 2: per-class d^2 over this tile's 16 dims (reload s from L2)
    #pragma unroll
    for (int j = 0; j < 4; j++) {
        int kk = t + j * 128;
        int c  = g_z.cnt[kk * PAD];
        if (c > 0) {
            float fc  = (float)c;
            float ip  = 1.f / fc;
            float in_ = 1.f / (fN - fc);
            float p = 0.f;
            #pragma unroll
            for (int cc = 0; cc < 4; cc++) {
                float4 a = make_float4(0.f, 0.f, 0.f, 0.f);
                #pragma unroll
                for (int hh = 0; hh < NSPL; hh++) {
                    float4 v = ((const float4*)g_sumsp[hh][kk])[cg0 + cc];
                    a.x += v.x; a.y += v.y; a.z += v.z; a.w += v.w;
                }
                float dx = a.x * ip - (Tt[cc].x - a.x) * in_ + 1e-6f;
                float dy = a.y * ip - (Tt[cc].y - a.y) * in_ + 1e-6f;
                float dz = a.z * ip - (Tt[cc].z - a.z) * in_ + 1e-6f;
                float dw = a.w * ip - (Tt[cc].w - a.w) * in_ + 1e-6f;
                p += dx * dx + dy * dy + dz * dz + dw * dw;
            }
            atomicAdd(&g_z.d2[kk * PAD], p);
        }
    }

    // ticket2: last volunteer finalizes
    __threadfence();
    __syncthreads();
    if (t == 0) s_t = atomicAdd(&g_z.tkt2, 1u);
    __syncthreads();
    if (s_t == VOL - 1) {
        __threadfence();
        float w = 0.f;
        #pragma unroll
        for (int j = 0; j < 4; j++) {
            int kk = t + j * 128;
            int c  = g_z.cnt[kk * PAD];
            if (c > 0) {
                float dist = sqrtf(g_z.d2[kk * PAD]);
                float mg = fmaxf(1.0f - dist, 0.f);    // MARGIN = 1.0
                w += (float)c * mg * mg;
            }
        }
        float* fr = (float*)&red[0][0];
        fr[t] = w;
        __syncthreads();
        #pragma unroll
        for (int sh = 64; sh > 0; sh >>= 1) {
            if (t < sh) fr[t] += fr[t + sh];
            __syncthreads();
        }
        if (t == 0) outp[0] = fr[0] / fN;
    }
}

// ---------------------------------------------------------------------------
extern "C" void kernel_launch(void* const* d_in, const int* in_sizes, int n_in,
                              void* d_out, int out_size)
{
    const float* output = (const float*)d_in[0];
    const int*   label  = (const int*)d_in[1];
    int N = in_sizes[1];

    void* zptr = nullptr;
    cudaGetSymbolAddress(&zptr, g_z);            // host-side query; capture-safe
    cudaMemsetAsync(zptr, 0, sizeof(ZeroBlk));   // counters + d2 + tickets + flag

    k_scatter<<<(N + 255) / 256, 256>>>(label, N);
    k_fused<<<NCTA, 128>>>(output, (float*)d_out, (float)N);
}

// round 12
// speedup vs baseline: 1.5304x; 1.5304x over previous
#include <cuda_runtime.h>

// ScatterLoss — per-class contrastive hinge loss.
// d_in[0] = output [N, D] float32 (N=65536, D=512)
// d_in[1] = label_id [N] int32
// out     = scalar float32
//
// loss = (1/N) * sum_k cnt_k * relu(1 - || s_k/c_k - (T - s_k)/(N - c_k) + 1e-6 ||_2)^2

#define NCLS 512
#define DDIM 512
#define NF4  (DDIM / 4)   // 128 float4 columns
#define CAP  1024         // max rows per class (counts ~128±11)
#define NSPL 4            // class split factor for the streaming kernel
#define PAD  32           // ints per 128B line — atomic-target padding

// Zeroed each replay by one memset node (0 bits == 0.0f == 0).
struct ZeroBlk {
    int   cnt[NCLS * PAD];
    float d2[NCLS * PAD];
    unsigned int ticket;
};
static __device__ ZeroBlk g_z;

static __device__ int   g_idx[NCLS * CAP];
static __device__ float g_sumsp[NSPL][NCLS][DDIM];   // per-quarter class sums

// ---------------------------------------------------------------------------
// K1: counting-sort scatter (R7-proven: one thread per label; 5.5us floor).
// Padded counters spread 65K atomics over 512 distinct 128B lines.
// ---------------------------------------------------------------------------
__global__ void k_scatter(const int* __restrict__ lab, int N)
{
    int i = blockIdx.x * blockDim.x + threadIdx.x;
    if (i < N) {
        int k = lab[i];
        if ((unsigned)k < NCLS) {
            int pos = atomicAdd(&g_z.cnt[k * PAD], 1);
            if (pos < CAP) g_idx[k * CAP + pos] = i;
        }
    }
}

// ---------------------------------------------------------------------------
// K2: per-class partial sums. Four CTAs per class (contiguous quarters of
// the row list). Index words load warp-uniform (broadcast); row data read
// exactly once (__ldcs evict-first). 2KB coalesced float4 row reads.
// unroll 16: the R11 profile proved this kernel is latency-limited (DRAM 30%
// at occ 40% when regs ballooned) — deeper per-thread MLP is the lever, and
// the standalone kernel is slim enough (~48 regs) to keep 16 loads in flight.
// ---------------------------------------------------------------------------
__global__ void __launch_bounds__(128) k_class_sum_q(const float* __restrict__ out)
{
    int k  = blockIdx.x >> 2;
    int h  = blockIdx.x & 3;
    int nk = min(g_z.cnt[k * PAD], CAP);
    int j0 = (h * nk) >> 2;
    int j1 = ((h + 1) * nk) >> 2;
    int nj = j1 - j0;

    const int* idx = g_idx + k * CAP + j0;
    int q = threadIdx.x;  // float4 column 0..127

    float4 acc = make_float4(0.f, 0.f, 0.f, 0.f);
    #pragma unroll 16
    for (int j = 0; j < nj; j++) {
        int r = __ldg(idx + j);                       // uniform -> broadcast
        const float4* row = (const float4*)(out + (size_t)r * DDIM);
        float4 v = __ldcs(row + q);                   // read-once: evict-first
        acc.x += v.x; acc.y += v.y; acc.z += v.z; acc.w += v.w;
    }
    ((float4*)g_sumsp[h][k])[q] = acc;
}

// ---------------------------------------------------------------------------
// K3: fused grand-total + per-class d^2 partials + last-CTA finalize
// (byte-for-byte the R7 version that measured 38.9 total).
// 32 CTAs x 256 threads; CTA owns 4 float4-columns, thread owns 2 classes.
// ---------------------------------------------------------------------------
__global__ void __launch_bounds__(256) k_colloss(float* __restrict__ outp, float fN)
{
    __shared__ float4 red[256];
    __shared__ unsigned int s_tkt;
    int t   = threadIdx.x;
    int cg0 = blockIdx.x * 4;          // first float4 column of this CTA

    // fold the 4 quarter-sums for 2 classes x 4 columns
    float4 s[2][4];
    #pragma unroll
    for (int m = 0; m < 2; m++) {
        int k = t + m * 256;
        #pragma unroll
        for (int cc = 0; cc < 4; cc++) {
            float4 a = make_float4(0.f, 0.f, 0.f, 0.f);
            #pragma unroll
            for (int h = 0; h < NSPL; h++) {
                float4 v = ((const float4*)g_sumsp[h][k])[cg0 + cc];
                a.x += v.x; a.y += v.y; a.z += v.z; a.w += v.w;
            }
            s[m][cc] = a;
        }
    }

    // grand total T for the 4 columns (sequential tree passes, R7-proven)
    float4 T[4];
    #pragma unroll
    for (int cc = 0; cc < 4; cc++) {
        float4 x;
        x.x = s[0][cc].x + s[1][cc].x; x.y = s[0][cc].y + s[1][cc].y;
        x.z = s[0][cc].z + s[1][cc].z; x.w = s[0][cc].w + s[1][cc].w;
        red[t] = x;
        __syncthreads();
        #pragma unroll
        for (int sh = 128; sh > 0; sh >>= 1) {
            if (t < sh) {
                float4 b = red[t + sh];
                red[t].x += b.x; red[t].y += b.y; red[t].z += b.z; red[t].w += b.w;
            }
            __syncthreads();
        }
        T[cc] = red[0];
        __syncthreads();
    }

    // per-class d^2 contribution over this CTA's 16 dims -> one atomic each
    #pragma unroll
    for (int m = 0; m < 2; m++) {
        int k = t + m * 256;
        int c = g_z.cnt[k * PAD];
        if (c > 0) {
            float fc  = (float)c;
            float ip  = 1.f / fc;
            float in_ = 1.f / (fN - fc);
            float p = 0.f;
            #pragma unroll
            for (int cc = 0; cc < 4; cc++) {
                float dx = s[m][cc].x * ip - (T[cc].x - s[m][cc].x) * in_ + 1e-6f;
                float dy = s[m][cc].y * ip - (T[cc].y - s[m][cc].y) * in_ + 1e-6f;
                float dz = s[m][cc].z * ip - (T[cc].z - s[m][cc].z) * in_ + 1e-6f;
                float dw = s[m][cc].w * ip - (T[cc].w - s[m][cc].w) * in_ + 1e-6f;
                p += dx * dx + dy * dy + dz * dz + dw * dw;
            }
            atomicAdd(&g_z.d2[k * PAD], p);
        }
    }

    // last-CTA finalize
    __threadfence();
    __syncthreads();
    if (t == 0) s_tkt = atomicAdd(&g_z.ticket, 1u);
    __syncthreads();
    if (s_tkt == (unsigned)(gridDim.x - 1)) {
        float w = 0.f;
        #pragma unroll
        for (int m = 0; m < 2; m++) {
            int k = t + m * 256;
            int c = g_z.cnt[k * PAD];
            if (c > 0) {
                float dist = sqrtf(g_z.d2[k * PAD]);
                float mg = fmaxf(1.0f - dist, 0.f);   // MARGIN = 1.0
                w += (float)c * mg * mg;
            }
        }
        ((float*)red)[t] = w;
        __syncthreads();
        #pragma unroll
        for (int sh = 128; sh > 0; sh >>= 1) {
            if (t < sh) ((float*)red)[t] += ((float*)red)[t + sh];
            __syncthreads();
        }
        if (t == 0) outp[0] = ((float*)red)[0] / fN;
    }
}

// ---------------------------------------------------------------------------
extern "C" void kernel_launch(void* const* d_in, const int* in_sizes, int n_in,
                              void* d_out, int out_size)
{
    const float* output = (const float*)d_in[0];
    const int*   label  = (const int*)d_in[1];
    int N = in_sizes[1];

    void* zptr = nullptr;
    cudaGetSymbolAddress(&zptr, g_z);            // host-side query; capture-safe
    cudaMemsetAsync(zptr, 0, sizeof(ZeroBlk));   // counters + d2 + ticket

    k_scatter<<<(N + 255) / 256, 256>>>(label, N);
    k_class_sum_q<<<NCLS * NSPL, 128>>>(output);
    k_colloss<<<NF4 / 4, 256>>>((float*)d_out, (float)N);
}

// round 13
// speedup vs baseline: 1.6139x; 1.0545x over previous
#include <cuda_runtime.h>

// ScatterLoss — per-class contrastive hinge loss.
// d_in[0] = output [N, D] float32 (N=65536, D=512)
// d_in[1] = label_id [N] int32
// out     = scalar float32
//
// loss = (1/N) * sum_k cnt_k * relu(1 - || s_k/c_k - (T - s_k)/(N - c_k) + 1e-6 ||_2)^2

#define NCLS 512
#define DDIM 512
#define NF4  (DDIM / 4)   // 128 float4 columns
#define CAP  1024         // max rows per class (counts ~128±11)
#define NSPL 4            // class split factor for the streaming kernel
#define PAD  32           // words per 128B line — atomic-target padding
#define DBANK 8           // d2 accumulator banks per class (within its line)

// Zeroed each replay by one memset node (0 bits == 0.0f == 0).
struct ZeroBlk {
    int   cnt[NCLS * PAD];
    float d2[NCLS * PAD];   // banks 0..7 of each class line used
    unsigned int ticket;
};
static __device__ ZeroBlk g_z;

static __device__ int   g_idx[NCLS * CAP];
static __device__ float g_sumsp[NSPL][NCLS][DDIM];   // per-quarter class sums

// ---------------------------------------------------------------------------
// K1: counting-sort scatter (proven floor: one thread per label, 5.4us).
// Padded counters spread 65K atomics over 512 distinct 128B lines.
// ---------------------------------------------------------------------------
__global__ void k_scatter(const int* __restrict__ lab, int N)
{
    int i = blockIdx.x * blockDim.x + threadIdx.x;
    if (i < N) {
        int k = lab[i];
        if ((unsigned)k < NCLS) {
            int pos = atomicAdd(&g_z.cnt[k * PAD], 1);
            if (pos < CAP) g_idx[k * CAP + pos] = i;
        }
    }
}

// ---------------------------------------------------------------------------
// K2: per-class partial sums (byte-identical to the 38.9us configuration).
// Four CTAs per class; warp-uniform index loads; 2KB coalesced float4 rows,
// __ldcs evict-first. Reads the full 128 MB matrix exactly once -> HBM bound.
// ---------------------------------------------------------------------------
__global__ void __launch_bounds__(128) k_class_sum_q(const float* __restrict__ out)
{
    int k  = blockIdx.x >> 2;
    int h  = blockIdx.x & 3;
    int nk = min(g_z.cnt[k * PAD], CAP);
    int j0 = (h * nk) >> 2;
    int j1 = ((h + 1) * nk) >> 2;
    int nj = j1 - j0;

    const int* idx = g_idx + k * CAP + j0;
    int q = threadIdx.x;  // float4 column 0..127

    float4 acc = make_float4(0.f, 0.f, 0.f, 0.f);
    #pragma unroll 16
    for (int j = 0; j < nj; j++) {
        int r = __ldg(idx + j);                       // uniform -> broadcast
        const float4* row = (const float4*)(out + (size_t)r * DDIM);
        float4 v = __ldcs(row + q);                   // read-once: evict-first
        acc.x += v.x; acc.y += v.y; acc.z += v.z; acc.w += v.w;
    }
    ((float4*)g_sumsp[h][k])[q] = acc;
}

// ---------------------------------------------------------------------------
// K3: grand-total + per-class d^2 partials + last-CTA finalize.
// 128 CTAs (one float4-column each -> near-full chip, single wave) x 256
// threads (2 classes each). Per thread: 8 L2-resident float4 loads, one
// 8-level tree for T, then a BANKED d^2 deposit: bank = blockIdx&7 within
// the class's padded line -> 65K atomics over 4096 addresses (16/addr),
// killing the serialization that forced 32 CTAs before. Last CTA folds the
// 8 banks per class and writes the count-weighted hinge mean.
// ---------------------------------------------------------------------------
__global__ void __launch_bounds__(256) k_colloss(float* __restrict__ outp, float fN)
{
    __shared__ float4 red[256];
    __shared__ unsigned int s_tkt;
    int cg = blockIdx.x;               // this CTA's float4 column
    int t  = threadIdx.x;
    int bank = blockIdx.x & (DBANK - 1);

    // fold the 4 quarter-sums for 2 classes
    float4 s[2];
    #pragma unroll
    for (int m = 0; m < 2; m++) {
        int k = t + m * 256;
        float4 a = make_float4(0.f, 0.f, 0.f, 0.f);
        #pragma unroll
        for (int h = 0; h < NSPL; h++) {
            float4 v = ((const float4*)g_sumsp[h][k])[cg];
            a.x += v.x; a.y += v.y; a.z += v.z; a.w += v.w;
        }
        s[m] = a;
    }

    // grand total T for this column (one 8-level tree)
    float4 x;
    x.x = s[0].x + s[1].x; x.y = s[0].y + s[1].y;
    x.z = s[0].z + s[1].z; x.w = s[0].w + s[1].w;
    red[t] = x;
    __syncthreads();
    #pragma unroll
    for (int sh = 128; sh > 0; sh >>= 1) {
        if (t < sh) {
            float4 b = red[t + sh];
            red[t].x += b.x; red[t].y += b.y; red[t].z += b.z; red[t].w += b.w;
        }
        __syncthreads();
    }
    float4 T = red[0];

    // per-class d^2 over this column's 4 dims -> banked atomic deposit
    #pragma unroll
    for (int m = 0; m < 2; m++) {
        int k = t + m * 256;
        int c = g_z.cnt[k * PAD];
        if (c > 0) {
            float fc  = (float)c;
            float ip  = 1.f / fc;
            float in_ = 1.f / (fN - fc);
            float dx = s[m].x * ip - (T.x - s[m].x) * in_ + 1e-6f;
            float dy = s[m].y * ip - (T.y - s[m].y) * in_ + 1e-6f;
            float dz = s[m].z * ip - (T.z - s[m].z) * in_ + 1e-6f;
            float dw = s[m].w * ip - (T.w - s[m].w) * in_ + 1e-6f;
            float p  = dx * dx + dy * dy + dz * dz + dw * dw;
            atomicAdd(&g_z.d2[k * PAD + bank], p);
        }
    }

    // last-CTA finalize
    __threadfence();
    __syncthreads();
    if (t == 0) s_tkt = atomicAdd(&g_z.ticket, 1u);
    __syncthreads();
    if (s_tkt == (unsigned)(gridDim.x - 1)) {
        __threadfence();
        float w = 0.f;
        #pragma unroll
        for (int m = 0; m < 2; m++) {
            int k = t + m * 256;
            int c = g_z.cnt[k * PAD];
            if (c > 0) {
                float d2 = 0.f;
                #pragma unroll
                for (int b = 0; b < DBANK; b++)
                    d2 += g_z.d2[k * PAD + b];
                float dist = sqrtf(d2);
                float mg = fmaxf(1.0f - dist, 0.f);   // MARGIN = 1.0
                w += (float)c * mg * mg;
            }
        }
        float* fr = (float*)red;
        fr[t] = w;
        __syncthreads();
        #pragma unroll
        for (int sh = 128; sh > 0; sh >>= 1) {
            if (t < sh) fr[t] += fr[t + sh];
            __syncthreads();
        }
        if (t == 0) outp[0] = fr[0] / fN;
    }
}

// ---------------------------------------------------------------------------
extern "C" void kernel_launch(void* const* d_in, const int* in_sizes, int n_in,
                              void* d_out, int out_size)
{
    const float* output = (const float*)d_in[0];
    const int*   label  = (const int*)d_in[1];
    int N = in_sizes[1];

    void* zptr = nullptr;
    cudaGetSymbolAddress(&zptr, g_z);            // host-side query; capture-safe
    cudaMemsetAsync(zptr, 0, sizeof(ZeroBlk));   // counters + d2 banks + ticket

    k_scatter<<<(N + 255) / 256, 256>>>(label, N);
    k_class_sum_q<<<NCLS * NSPL, 128>>>(output);
    k_colloss<<<NF4, 256>>>((float*)d_out, (float)N);
}